// round 8
// baseline (speedup 1.0000x reference)
#include <cuda_runtime.h>
#include <cuda_bf16.h>
#include <cstdint>

#define T_SEQ   80
#define NCLS    80
#define HID     256
#define EMB     8
#define BATCH   8192
#define GATES   1024
#define M_CTA   64
#define NCTA    (BATCH / M_CTA)
#define NTHREADS 512

#define KT1     17                  // layer1 K = 272 (1 bias + 7 pad + 8 x + 256 h1)
#define KT2     33                  // layer2 K = 528 (adds 256 h2)
#define A_STRIDE   536              // bf16 elems/row; 1072B % 128 = 48 -> conflict-free ldmatrix
#define A_STRIDE_B (A_STRIDE * 2)
#define C_STRIDE   264

#define SM_A        0
#define SM_A_BYTES  (M_CTA * A_STRIDE_B)
#define SM_C1       SM_A_BYTES
#define SM_CBYTES   (M_CTA * C_STRIDE * 4)
#define SM_C2       (SM_C1 + SM_CBYTES)
#define SM_EMB      (SM_C2 + SM_CBYTES)
#define SM_LOGITS   (SM_EMB + NCLS * EMB * 4)
#define SM_TOTAL    (SM_LOGITS + M_CTA * NCLS * 4)   // 226816 bytes

// Packed weights, gate-interleaved fragment-major:
//   uint2 index = ((nt*KT + kt)*32 + lane)*4 + gi,  nt in [0,32), gi in [0,4)
// Column n = gi*256 + nt*8 + (lane>>2); rows k0,k0+1,k0+8,k0+9, k0 = kt*16+(lane&3)*2.
#define N1PK (32 * KT1 * 128)
#define N2PK (32 * KT2 * 128)
__device__ uint4 g_W1p[32 * KT1 * 64];
__device__ uint4 g_W2p[32 * KT2 * 64];

__global__ void pack_all(const float* __restrict__ W1, const float* __restrict__ b1,
                         const float* __restrict__ W2, const float* __restrict__ b2)
{
    int idx = blockIdx.x * blockDim.x + threadIdx.x;
    if (idx >= N1PK + N2PK) return;
    const float *W, *b; uint2* out; int KT, woff, rem;
    if (idx < N1PK) { W = W1; b = b1; out = (uint2*)g_W1p; KT = KT1; woff = 8;  rem = idx; }
    else            { W = W2; b = b2; out = (uint2*)g_W2p; KT = KT2; woff = 16; rem = idx - N1PK; }
    int gi   = rem & 3;
    int lane = (rem >> 2) & 31;
    int t    = rem >> 7;
    int kt   = t % KT;
    int nt   = t / KT;
    int th = lane & 3, g = lane >> 2;
    int n  = gi * 256 + nt * 8 + g;
    int k0 = kt * 16 + th * 2;
    float v[4];
#pragma unroll
    for (int i = 0; i < 4; i++) {
        int r = k0 + ((i >> 1) * 8) + (i & 1);
        float val;
        if (r == 0)          val = b[n];
        else if (r < woff)   val = 0.f;
        else                 val = W[(size_t)(r - woff) * GATES + n];
        v[i] = val;
    }
    __nv_bfloat162 p0 = __floats2bfloat162_rn(v[0], v[1]);
    __nv_bfloat162 p1 = __floats2bfloat162_rn(v[2], v[3]);
    uint2 o;
    o.x = *reinterpret_cast<uint32_t*>(&p0);
    o.y = *reinterpret_cast<uint32_t*>(&p1);
    out[rem] = o;
}

__device__ __forceinline__ float fast_tanh(float x) {
    float y; asm("tanh.approx.f32 %0, %1;" : "=f"(y) : "f"(x)); return y;
}
__device__ __forceinline__ float fast_sigmoid(float x) {
    return fmaf(fast_tanh(0.5f * x), 0.5f, 0.5f);
}
__device__ __forceinline__ void ldsm4(uint32_t a[4], uint32_t addr) {
    asm volatile("ldmatrix.sync.aligned.m8n8.x4.shared.b16 {%0,%1,%2,%3}, [%4];\n"
                 : "=r"(a[0]), "=r"(a[1]), "=r"(a[2]), "=r"(a[3]) : "r"(addr));
}
__device__ __forceinline__ void mma_bf16(float c[4], const uint32_t a[4], uint32_t b0, uint32_t b1) {
    asm volatile("mma.sync.aligned.m16n8k16.row.col.f32.bf16.bf16.f32 "
                 "{%0,%1,%2,%3}, {%4,%5,%6,%7}, {%8,%9}, {%0,%1,%2,%3};\n"
                 : "+f"(c[0]), "+f"(c[1]), "+f"(c[2]), "+f"(c[3])
                 : "r"(a[0]), "r"(a[1]), "r"(a[2]), "r"(a[3]), "r"(b0), "r"(b1));
}

// One LSTM layer for 64 rows, 16 warps: wm = M-half (32 rows), wn = N-slice.
// Warp (wm,wn), cblk: rows [wm*32, +32), hidden cols [cblk*64+wn*8, +8), all 4 gates.
template<int KT>
__device__ __forceinline__ void lstm_layer(
    uint32_t sbase, const uint4* __restrict__ Wp,
    float* __restrict__ cbuf, uint32_t (&hnew)[4][2][2],
    int wm, int wn, int lane)
{
    const int th = lane & 3, g = lane >> 2;
    const uint32_t a_base = sbase +
        (uint32_t)((wm * 32 + (lane & 15)) * A_STRIDE_B + ((lane >> 4) << 4));

#pragma unroll
    for (int cblk = 0; cblk < 4; cblk++) {
        float acc[2][4][4];
#pragma unroll
        for (int mt = 0; mt < 2; mt++)
#pragma unroll
            for (int gi = 0; gi < 4; gi++)
#pragma unroll
                for (int i = 0; i < 4; i++) acc[mt][gi][i] = 0.f;

        const uint4* bb = Wp + ((size_t)((cblk * 8 + wn) * KT) * 32 + lane) * 2;
        uint4 b0a = __ldg(bb),       b0b = __ldg(bb + 1);
        uint4 b1a = __ldg(bb + 64),  b1b = __ldg(bb + 65);
        uint4 b2a = __ldg(bb + 128), b2b = __ldg(bb + 129);
        bb += 192;

        uint32_t af[2][4];
        uint32_t aaddr = a_base;
#pragma unroll
        for (int mt = 0; mt < 2; mt++)
            ldsm4(af[mt], aaddr + (uint32_t)(mt * (16 * A_STRIDE_B)));
        aaddr += 32;

#pragma unroll 1
        for (int kt = 0; kt < KT; kt++) {
            uint4 nb0 = {0,0,0,0}, nb1 = {0,0,0,0};
            if (kt + 3 < KT) { nb0 = __ldg(bb); nb1 = __ldg(bb + 1); }
            bb += 64;
#pragma unroll
            for (int mt = 0; mt < 2; mt++) {
                mma_bf16(acc[mt][0], af[mt], b0a.x, b0a.y);
                mma_bf16(acc[mt][1], af[mt], b0a.z, b0a.w);
                mma_bf16(acc[mt][2], af[mt], b0b.x, b0b.y);
                mma_bf16(acc[mt][3], af[mt], b0b.z, b0b.w);
            }
            if (kt + 1 < KT) {
#pragma unroll
                for (int mt = 0; mt < 2; mt++)
                    ldsm4(af[mt], aaddr + (uint32_t)(mt * (16 * A_STRIDE_B)));
                aaddr += 32;
            }
            b0a = b1a; b0b = b1b; b1a = b2a; b1b = b2b; b2a = nb0; b2b = nb1;
        }

        // elementwise for this cblk (i=0, j=1, f=2, o=3)
        const int hcol = cblk * 64 + wn * 8 + th * 2;
#pragma unroll
        for (int mt = 0; mt < 2; mt++) {
#pragma unroll
            for (int half = 0; half < 2; half++) {
                const int r = wm * 32 + mt * 16 + g + half * 8;
                uint32_t hn = 0;
#pragma unroll
                for (int p = 0; p < 2; p++) {
                    const int ci = half * 2 + p;
                    float* cp = cbuf + r * C_STRIDE + hcol + p;
                    float nc = (*cp) * fast_sigmoid(acc[mt][2][ci] + 1.0f)
                             + fast_sigmoid(acc[mt][0][ci]) * fast_tanh(acc[mt][1][ci]);
                    *cp = nc;
                    float hv = fast_tanh(nc) * fast_sigmoid(acc[mt][3][ci]);
                    unsigned short us = __bfloat16_as_ushort(__float2bfloat16(hv));
                    hn |= ((uint32_t)us) << (16 * p);
                }
                hnew[cblk][mt][half] = hn;
            }
        }
    }
}

__device__ __forceinline__ void store_h(char* smem, const uint32_t (&hnew)[4][2][2],
                                        int hoff, int wm, int wn, int lane)
{
    const int th = lane & 3, g = lane >> 2;
#pragma unroll
    for (int cblk = 0; cblk < 4; cblk++) {
        const int col = hoff + cblk * 64 + wn * 8 + th * 2;
#pragma unroll
        for (int mt = 0; mt < 2; mt++)
#pragma unroll
            for (int half = 0; half < 2; half++) {
                const int r = wm * 32 + mt * 16 + g + half * 8;
                *reinterpret_cast<uint32_t*>(smem + r * A_STRIDE_B + col * 2) = hnew[cblk][mt][half];
            }
    }
}

__device__ __forceinline__ void write_x(char* smem, float* embs,
                                        const int* __restrict__ features,
                                        int rowbase, int t, int tid)
{
    if (tid < M_CTA) {
        int f = features[(rowbase + tid) * T_SEQ + t];
        const float* e = embs + f * EMB;
        uint32_t* dst = reinterpret_cast<uint32_t*>(smem + tid * A_STRIDE_B + 16);
#pragma unroll
        for (int i = 0; i < 4; i++) {
            __nv_bfloat162 p = __floats2bfloat162_rn(e[2 * i], e[2 * i + 1]);
            dst[i] = *reinterpret_cast<uint32_t*>(&p);
        }
    }
}

__global__ void __launch_bounds__(NTHREADS, 1) lstm_kernel(
    const int* __restrict__ features, const int* __restrict__ labels,
    const float* __restrict__ embedding,
    const float* __restrict__ Wd, const float* __restrict__ bd,
    float* __restrict__ out)
{
    extern __shared__ char smem[];
    const int tid = threadIdx.x;
    const int w = tid >> 5, lane = tid & 31;
    const int wm = w >> 3, wn = w & 7;
    const int rowbase = blockIdx.x * M_CTA;

    float* c1   = (float*)(smem + SM_C1);
    float* c2   = (float*)(smem + SM_C2);
    float* embs = (float*)(smem + SM_EMB);

    for (int i = tid; i < SM_TOTAL / 4; i += NTHREADS)
        ((uint32_t*)smem)[i] = 0u;
    __syncthreads();
    if (tid < M_CTA)
        *reinterpret_cast<__nv_bfloat16*>(smem + tid * A_STRIDE_B) = __float2bfloat16(1.0f);
    for (int i = tid; i < NCLS * EMB; i += NTHREADS) embs[i] = embedding[i];
    __syncthreads();
    write_x(smem, embs, features, rowbase, 0, tid);
    __syncthreads();

    const uint32_t sbase = (uint32_t)__cvta_generic_to_shared(smem);
    uint32_t hnew[4][2][2];

    for (int t = 0; t < T_SEQ; t++) {
        lstm_layer<KT1>(sbase, g_W1p, c1, hnew, wm, wn, lane);
        __syncthreads();
        store_h(smem, hnew, 16, wm, wn, lane);                  // h1 -> cols 16..271
        if (t + 1 < T_SEQ) write_x(smem, embs, features, rowbase, t + 1, tid);
        __syncthreads();   // layer2 reads x-cols against ZERO weight rows: values don't-care
        lstm_layer<KT2>(sbase, g_W2p, c2, hnew, wm, wn, lane);
        __syncthreads();
        store_h(smem, hnew, 272, wm, wn, lane);                 // h2 -> cols 272..527
        __syncthreads();
    }

    // dense + log-softmax loss
    float* logits = (float*)(smem + SM_LOGITS);
    for (int item = tid; item < M_CTA * NCLS; item += NTHREADS) {
        int row = item / NCLS, cls = item - row * NCLS;
        const __nv_bfloat16* h2p = (const __nv_bfloat16*)(smem + row * A_STRIDE_B + 272 * 2);
        float acc = __ldg(&bd[cls]);
#pragma unroll 8
        for (int k = 0; k < HID; k++)
            acc += __bfloat162float(h2p[k]) * __ldg(&Wd[k * NCLS + cls]);
        logits[item] = acc;
    }
    __syncthreads();
    if (tid < M_CTA) {
        const float* lr = logits + tid * NCLS;
        float mx = -1e30f;
        for (int c = 0; c < NCLS; c++) mx = fmaxf(mx, lr[c]);
        float s = 0.f;
        for (int c = 0; c < NCLS; c++) s += __expf(lr[c] - mx);
        int lab = labels[rowbase + tid];
        out[rowbase + tid] = mx + __logf(s) - lr[lab];
    }
}

extern "C" void kernel_launch(void* const* d_in, const int* in_sizes, int n_in,
                              void* d_out, int out_size)
{
    const int*   features  = (const int*)  d_in[0];
    const int*   labels    = (const int*)  d_in[1];
    const float* embedding = (const float*)d_in[2];
    const float* W1        = (const float*)d_in[3];
    const float* b1        = (const float*)d_in[4];
    const float* W2        = (const float*)d_in[5];
    const float* b2        = (const float*)d_in[6];
    const float* Wd        = (const float*)d_in[7];
    const float* bd        = (const float*)d_in[8];
    float* out = (float*)d_out;

    int ntot = N1PK + N2PK;
    pack_all<<<(ntot + 255) / 256, 256>>>(W1, b1, W2, b2);

    cudaFuncSetAttribute(lstm_kernel, cudaFuncAttributeMaxDynamicSharedMemorySize, SM_TOTAL);
    lstm_kernel<<<NCTA, NTHREADS, SM_TOTAL>>>(features, labels, embedding, Wd, bd, out);
}

// round 10
// speedup vs baseline: 1.1686x; 1.1686x over previous
#include <cuda_runtime.h>
#include <cuda_bf16.h>
#include <cstdint>

#define T_SEQ   80
#define NCLS    80
#define HID     256
#define EMB     8
#define BATCH   8192
#define GATES   1024
#define M_CTA   64
#define NCTA    (BATCH / M_CTA)
#define NTHREADS 512

#define KT1     18                  // layer1 K = 288 (1 bias + 7 pad + 8 x + 256 h1 + 16 zero-pad), %3==0
#define KT2     33                  // layer2 K = 528, %3==0
#define A_STRIDE   536              // bf16 elems/row; 1072B % 128 = 48 -> conflict-free ldmatrix
#define A_STRIDE_B (A_STRIDE * 2)
#define C_STRIDE   264

#define SM_A        0
#define SM_A_BYTES  (M_CTA * A_STRIDE_B)
#define SM_C1       SM_A_BYTES
#define SM_CBYTES   (M_CTA * C_STRIDE * 4)
#define SM_C2       (SM_C1 + SM_CBYTES)
#define SM_EMB      (SM_C2 + SM_CBYTES)
#define SM_LOGITS   (SM_EMB + NCLS * EMB * 4)
#define SM_TOTAL    (SM_LOGITS + M_CTA * NCLS * 4)   // 226816 bytes

// Packed weights, gate-interleaved fragment-major:
//   uint2 index = ((nt*KT + kt)*32 + lane)*4 + gi,  nt in [0,32), gi in [0,4)
// Column n = gi*256 + nt*8 + (lane>>2); rows k0,k0+1,k0+8,k0+9, k0 = kt*16+(lane&3)*2.
#define N1PK (32 * KT1 * 128)
#define N2PK (32 * KT2 * 128)
__device__ uint4 g_W1p[32 * KT1 * 64];
__device__ uint4 g_W2p[32 * KT2 * 64];

// Extended row r: r==0 -> bias[n]; r<woff or r>=rmax -> 0; else W[r-woff][n]
__global__ void pack_all(const float* __restrict__ W1, const float* __restrict__ b1,
                         const float* __restrict__ W2, const float* __restrict__ b2)
{
    int idx = blockIdx.x * blockDim.x + threadIdx.x;
    if (idx >= N1PK + N2PK) return;
    const float *W, *b; uint2* out; int KT, woff, rmax, rem;
    if (idx < N1PK) { W = W1; b = b1; out = (uint2*)g_W1p; KT = KT1; woff = 8;  rmax = 272; rem = idx; }
    else            { W = W2; b = b2; out = (uint2*)g_W2p; KT = KT2; woff = 16; rmax = 528; rem = idx - N1PK; }
    int gi   = rem & 3;
    int lane = (rem >> 2) & 31;
    int t    = rem >> 7;
    int kt   = t % KT;
    int nt   = t / KT;
    int th = lane & 3, g = lane >> 2;
    int n  = gi * 256 + nt * 8 + g;
    int k0 = kt * 16 + th * 2;
    float v[4];
#pragma unroll
    for (int i = 0; i < 4; i++) {
        int r = k0 + ((i >> 1) * 8) + (i & 1);
        float val;
        if (r == 0)                    val = b[n];
        else if (r < woff || r >= rmax) val = 0.f;
        else                           val = W[(size_t)(r - woff) * GATES + n];
        v[i] = val;
    }
    __nv_bfloat162 p0 = __floats2bfloat162_rn(v[0], v[1]);
    __nv_bfloat162 p1 = __floats2bfloat162_rn(v[2], v[3]);
    uint2 o;
    o.x = *reinterpret_cast<uint32_t*>(&p0);
    o.y = *reinterpret_cast<uint32_t*>(&p1);
    out[rem] = o;
}

__device__ __forceinline__ float fast_tanh(float x) {
    float y; asm("tanh.approx.f32 %0, %1;" : "=f"(y) : "f"(x)); return y;
}
__device__ __forceinline__ float fast_sigmoid(float x) {
    return fmaf(fast_tanh(0.5f * x), 0.5f, 0.5f);
}
__device__ __forceinline__ void ldsm4(uint32_t a[4], uint32_t addr) {
    asm volatile("ldmatrix.sync.aligned.m8n8.x4.shared.b16 {%0,%1,%2,%3}, [%4];\n"
                 : "=r"(a[0]), "=r"(a[1]), "=r"(a[2]), "=r"(a[3]) : "r"(addr));
}
__device__ __forceinline__ void mma_bf16(float c[4], const uint32_t a[4], uint32_t b0, uint32_t b1) {
    asm volatile("mma.sync.aligned.m16n8k16.row.col.f32.bf16.bf16.f32 "
                 "{%0,%1,%2,%3}, {%4,%5,%6,%7}, {%8,%9}, {%0,%1,%2,%3};\n"
                 : "+f"(c[0]), "+f"(c[1]), "+f"(c[2]), "+f"(c[3])
                 : "r"(a[0]), "r"(a[1]), "r"(a[2]), "r"(a[3]), "r"(b0), "r"(b1));
}

__device__ __forceinline__ void do_mmas(float (&acc)[2][4][4], const uint32_t (&af)[2][4],
                                        const uint4& x0, const uint4& x1)
{
#pragma unroll
    for (int mt = 0; mt < 2; mt++) {
        mma_bf16(acc[mt][0], af[mt], x0.x, x0.y);
        mma_bf16(acc[mt][1], af[mt], x0.z, x0.w);
        mma_bf16(acc[mt][2], af[mt], x1.x, x1.y);
        mma_bf16(acc[mt][3], af[mt], x1.z, x1.w);
    }
}

// One LSTM layer for 64 rows, 16 warps: wm = M-half (32 rows), wn = N-slice.
// B operand: 3-set rotating buffer in an unroll-by-3 loop (no register shifts).
template<int KT>
__device__ __forceinline__ void lstm_layer(
    uint32_t sbase, const uint4* __restrict__ Wp,
    float* __restrict__ cbuf, uint32_t (&hnew)[4][2][2],
    int wm, int wn, int lane)
{
    static_assert(KT % 3 == 0, "KT must be divisible by 3");
    const int th = lane & 3, g = lane >> 2;
    const uint32_t a_base = sbase +
        (uint32_t)((wm * 32 + (lane & 15)) * A_STRIDE_B + ((lane >> 4) << 4));

#pragma unroll
    for (int cblk = 0; cblk < 4; cblk++) {
        float acc[2][4][4];
#pragma unroll
        for (int mt = 0; mt < 2; mt++)
#pragma unroll
            for (int gi = 0; gi < 4; gi++)
#pragma unroll
                for (int i = 0; i < 4; i++) acc[mt][gi][i] = 0.f;

        const uint4* bb = Wp + ((size_t)((cblk * 8 + wn) * KT) * 32 + lane) * 2;
        uint4 A0 = __ldg(bb + 0),   A1 = __ldg(bb + 1);     // kt+0
        uint4 B0 = __ldg(bb + 64),  B1 = __ldg(bb + 65);    // kt+1
        uint4 C0 = __ldg(bb + 128), C1 = __ldg(bb + 129);   // kt+2

        uint32_t af[2][4];
        uint32_t am0 = a_base;
        uint32_t am1 = a_base + 16 * A_STRIDE_B;
        ldsm4(af[0], am0); ldsm4(af[1], am1);

#pragma unroll 1
        for (int kt = 0; kt < KT; kt += 3) {
            // substep 0 (kt): consume A-set, refill at kt+3
            do_mmas(acc, af, A0, A1);
            ldsm4(af[0], am0 + 32); ldsm4(af[1], am1 + 32);
            if (kt + 3 < KT) { A0 = __ldg(bb + 192); A1 = __ldg(bb + 193); }
            // substep 1 (kt+1): consume B-set, refill at kt+4
            do_mmas(acc, af, B0, B1);
            ldsm4(af[0], am0 + 64); ldsm4(af[1], am1 + 64);
            if (kt + 4 < KT) { B0 = __ldg(bb + 256); B1 = __ldg(bb + 257); }
            // substep 2 (kt+2): consume C-set, refill at kt+5
            do_mmas(acc, af, C0, C1);
            if (kt + 3 < KT) { ldsm4(af[0], am0 + 96); ldsm4(af[1], am1 + 96); }
            if (kt + 5 < KT) { C0 = __ldg(bb + 320); C1 = __ldg(bb + 321); }
            bb += 192; am0 += 96; am1 += 96;
        }

        // elementwise for this cblk (i=0, j=1, f=2, o=3)
        const int hcol = cblk * 64 + wn * 8 + th * 2;
#pragma unroll
        for (int mt = 0; mt < 2; mt++) {
#pragma unroll
            for (int half = 0; half < 2; half++) {
                const int r = wm * 32 + mt * 16 + g + half * 8;
                uint32_t hn = 0;
#pragma unroll
                for (int p = 0; p < 2; p++) {
                    const int ci = half * 2 + p;
                    float* cp = cbuf + r * C_STRIDE + hcol + p;
                    float nc = (*cp) * fast_sigmoid(acc[mt][2][ci] + 1.0f)
                             + fast_sigmoid(acc[mt][0][ci]) * fast_tanh(acc[mt][1][ci]);
                    *cp = nc;
                    float hv = fast_tanh(nc) * fast_sigmoid(acc[mt][3][ci]);
                    unsigned short us = __bfloat16_as_ushort(__float2bfloat16(hv));
                    hn |= ((uint32_t)us) << (16 * p);
                }
                hnew[cblk][mt][half] = hn;
            }
        }
    }
}

__device__ __forceinline__ void store_h(char* smem, const uint32_t (&hnew)[4][2][2],
                                        int hoff, int wm, int wn, int lane)
{
    const int th = lane & 3, g = lane >> 2;
#pragma unroll
    for (int cblk = 0; cblk < 4; cblk++) {
        const int col = hoff + cblk * 64 + wn * 8 + th * 2;
#pragma unroll
        for (int mt = 0; mt < 2; mt++)
#pragma unroll
            for (int half = 0; half < 2; half++) {
                const int r = wm * 32 + mt * 16 + g + half * 8;
                *reinterpret_cast<uint32_t*>(smem + r * A_STRIDE_B + col * 2) = hnew[cblk][mt][half];
            }
    }
}

__device__ __forceinline__ void write_x(char* smem, float* embs,
                                        const int* __restrict__ features,
                                        int rowbase, int t, int tid)
{
    if (tid < M_CTA) {
        int f = features[(rowbase + tid) * T_SEQ + t];
        const float* e = embs + f * EMB;
        uint32_t* dst = reinterpret_cast<uint32_t*>(smem + tid * A_STRIDE_B + 16);
#pragma unroll
        for (int i = 0; i < 4; i++) {
            __nv_bfloat162 p = __floats2bfloat162_rn(e[2 * i], e[2 * i + 1]);
            dst[i] = *reinterpret_cast<uint32_t*>(&p);
        }
    }
}

__global__ void __launch_bounds__(NTHREADS, 1) lstm_kernel(
    const int* __restrict__ features, const int* __restrict__ labels,
    const float* __restrict__ embedding,
    const float* __restrict__ Wd, const float* __restrict__ bd,
    float* __restrict__ out)
{
    extern __shared__ char smem[];
    const int tid = threadIdx.x;
    const int w = tid >> 5, lane = tid & 31;
    const int wm = w >> 3, wn = w & 7;
    const int rowbase = blockIdx.x * M_CTA;

    float* c1   = (float*)(smem + SM_C1);
    float* c2   = (float*)(smem + SM_C2);
    float* embs = (float*)(smem + SM_EMB);

    for (int i = tid; i < SM_TOTAL / 4; i += NTHREADS)
        ((uint32_t*)smem)[i] = 0u;
    __syncthreads();
    if (tid < M_CTA)
        *reinterpret_cast<__nv_bfloat16*>(smem + tid * A_STRIDE_B) = __float2bfloat16(1.0f);
    for (int i = tid; i < NCLS * EMB; i += NTHREADS) embs[i] = embedding[i];
    __syncthreads();
    write_x(smem, embs, features, rowbase, 0, tid);
    __syncthreads();

    const uint32_t sbase = (uint32_t)__cvta_generic_to_shared(smem);
    uint32_t hnew[4][2][2];

    for (int t = 0; t < T_SEQ; t++) {
        lstm_layer<KT1>(sbase, g_W1p, c1, hnew, wm, wn, lane);
        __syncthreads();
        store_h(smem, hnew, 16, wm, wn, lane);                  // h1 -> cols 16..271
        if (t + 1 < T_SEQ) write_x(smem, embs, features, rowbase, t + 1, tid);
        __syncthreads();   // layer2 reads x-cols against ZERO weight rows: values don't-care
        lstm_layer<KT2>(sbase, g_W2p, c2, hnew, wm, wn, lane);
        __syncthreads();
        store_h(smem, hnew, 272, wm, wn, lane);                 // h2 -> cols 272..527
        __syncthreads();
    }

    // dense + log-softmax loss
    float* logits = (float*)(smem + SM_LOGITS);
    for (int item = tid; item < M_CTA * NCLS; item += NTHREADS) {
        int row = item / NCLS, cls = item - row * NCLS;
        const __nv_bfloat16* h2p = (const __nv_bfloat16*)(smem + row * A_STRIDE_B + 272 * 2);
        float acc = __ldg(&bd[cls]);
#pragma unroll 8
        for (int k = 0; k < HID; k++)
            acc += __bfloat162float(h2p[k]) * __ldg(&Wd[k * NCLS + cls]);
        logits[item] = acc;
    }
    __syncthreads();
    if (tid < M_CTA) {
        const float* lr = logits + tid * NCLS;
        float mx = -1e30f;
        for (int c = 0; c < NCLS; c++) mx = fmaxf(mx, lr[c]);
        float s = 0.f;
        for (int c = 0; c < NCLS; c++) s += __expf(lr[c] - mx);
        int lab = labels[rowbase + tid];
        out[rowbase + tid] = mx + __logf(s) - lr[lab];
    }
}

extern "C" void kernel_launch(void* const* d_in, const int* in_sizes, int n_in,
                              void* d_out, int out_size)
{
    const int*   features  = (const int*)  d_in[0];
    const int*   labels    = (const int*)  d_in[1];
    const float* embedding = (const float*)d_in[2];
    const float* W1        = (const float*)d_in[3];
    const float* b1        = (const float*)d_in[4];
    const float* W2        = (const float*)d_in[5];
    const float* b2        = (const float*)d_in[6];
    const float* Wd        = (const float*)d_in[7];
    const float* bd        = (const float*)d_in[8];
    float* out = (float*)d_out;

    int ntot = N1PK + N2PK;
    pack_all<<<(ntot + 255) / 256, 256>>>(W1, b1, W2, b2);

    cudaFuncSetAttribute(lstm_kernel, cudaFuncAttributeMaxDynamicSharedMemorySize, SM_TOTAL);
    lstm_kernel<<<NCTA, NTHREADS, SM_TOTAL>>>(features, labels, embedding, Wd, bd, out);
}